// round 9
// baseline (speedup 1.0000x reference)
#include <cuda_runtime.h>
#include <math.h>
#include <cstdint>

// ---------------------------------------------------------------------------
// PreQ round 9: ONE fused kernel. Each CTA (512 thr, 16 warps = 4m x 4n)
// processes 128 rows through L1(300->224pad) -> L2(->128pad) -> L3(->64pad)
// -> layer4 + quantum fidelity. h1/h2 live in SMEM; only x is streamed from
// DRAM; W fragment images are tiny and L2-resident.
// tf32 mma.sync m16n8k8 (validated rounds 6-8, rel_err 1.28e-4).
// ---------------------------------------------------------------------------

#define MROWS 131072   // 2 * 65536

__device__ __align__(16) unsigned char g_w1f[224 * 1280];
__device__ __align__(16) unsigned char g_w2f[128 * 896];
__device__ __align__(16) unsigned char g_w3f[64 * 512];

// ---------------- helpers ----------------
__device__ __forceinline__ uint32_t smem_u32(const void* p) {
    uint32_t a;
    asm("{ .reg .u64 t; cvta.to.shared.u64 t, %1; cvt.u32.u64 %0, t; }"
        : "=r"(a) : "l"(p));
    return a;
}
__device__ __forceinline__ void cpa16(uint32_t dst, const void* src) {
    asm volatile("cp.async.cg.shared.global [%0], [%1], 16;"
                 :: "r"(dst), "l"(src) : "memory");
}
__device__ __forceinline__ void cpa16z(uint32_t dst, const void* src, int sz) {
    asm volatile("cp.async.cg.shared.global [%0], [%1], 16, %2;"
                 :: "r"(dst), "l"(src), "r"(sz) : "memory");
}
#define CP_COMMIT() asm volatile("cp.async.commit_group;" ::: "memory")
#define CP_WAIT0()  asm volatile("cp.async.wait_group 0;" ::: "memory")
#define CP_WAIT1()  asm volatile("cp.async.wait_group 1;" ::: "memory")

__device__ __forceinline__ uint32_t to_tf32(float f) {
    uint32_t r;
    asm("cvt.rna.tf32.f32 %0, %1;" : "=r"(r) : "f"(f));
    return r;
}
__device__ __forceinline__ void mma_tf32(float c[4],
                                         uint32_t a0, uint32_t a1,
                                         uint32_t a2, uint32_t a3,
                                         uint32_t b0, uint32_t b1) {
    asm volatile(
        "mma.sync.aligned.m16n8k8.row.col.f32.tf32.tf32.f32 "
        "{%0,%1,%2,%3}, {%4,%5,%6,%7}, {%8,%9}, {%0,%1,%2,%3};"
        : "+f"(c[0]), "+f"(c[1]), "+f"(c[2]), "+f"(c[3])
        : "r"(a0), "r"(a1), "r"(a2), "r"(a3), "r"(b0), "r"(b1));
}

// ---------------------------------------------------------------------------
// prep: W[src_rows, K] fp32 -> frag image [nrows_pad][nblk*64B], RN tf32.
// entry tp of k16-block eb = {k0+tp, k0+tp+4, k0+tp+8, k0+tp+12}, k0=16*eb.
// ---------------------------------------------------------------------------
__global__ void prep_frag(const float* __restrict__ S,
                          unsigned char* __restrict__ D,
                          int nrows_pad, int src_rows, int K, int nblk) {
    int f = blockIdx.x * blockDim.x + threadIdx.x;
    if (f >= nrows_pad * nblk) return;
    int row = f / nblk, eb = f - row * nblk;
    int k0 = eb * 16;
    float v[16];
    #pragma unroll
    for (int i = 0; i < 16; i++) v[i] = 0.f;
    if (row < src_rows) {
        #pragma unroll
        for (int i = 0; i < 4; i++) {
            int k = k0 + i * 4;
            if (k < K) {
                float4 q = *(const float4*)(S + (size_t)row * K + k);
                v[i * 4 + 0] = q.x; v[i * 4 + 1] = q.y;
                v[i * 4 + 2] = q.z; v[i * 4 + 3] = q.w;
            }
        }
    }
    uint32_t u[16];
    #pragma unroll
    for (int i = 0; i < 16; i++) u[i] = to_tf32(v[i]);
    unsigned char* dst = D + (size_t)row * (nblk * 64) + (size_t)eb * 64;
    #pragma unroll
    for (int tp = 0; tp < 4; tp++)
        *(uint4*)(dst + tp * 16) =
            make_uint4(u[tp], u[tp + 4], u[tp + 8], u[tp + 12]);
}

// ---------------- quantum math (verified rounds 1-8) ----------------
__device__ __forceinline__ float2 cadd(float2 a, float2 b) {
    return make_float2(a.x + b.x, a.y + b.y);
}
__device__ __forceinline__ float2 csc(float s, float2 a) {
    return make_float2(s * a.x, s * a.y);
}
__device__ __forceinline__ float2 cni(float s, float2 a) {
    return make_float2(s * a.y, -s * a.x);
}
__device__ void applyU(const float* __restrict__ p, float2 x[4]) {
    float c4, s4;
    __sincosf(0.5f * p[4], &s4, &c4);
    float2 y1 = make_float2(c4 * x[1].x + s4 * x[3].y,
                            c4 * x[1].y - s4 * x[3].x);
    float2 y3 = make_float2(s4 * x[1].y + c4 * x[3].x,
                           -s4 * x[1].x + c4 * x[3].y);
    x[1] = y1; x[3] = y3;
    float c2, s2, c3, s3;
    __sincosf(0.5f * p[2], &s2, &c2);
    __sincosf(0.5f * p[3], &s3, &c3);
    float2 t00 = cadd(csc(c3, x[0]), csc(-s3, x[1]));
    float2 t01 = cadd(csc(s3, x[0]), csc( c3, x[1]));
    float2 t10 = cadd(csc(c3, x[2]), csc(-s3, x[3]));
    float2 t11 = cadd(csc(s3, x[2]), csc( c3, x[3]));
    x[0] = cadd(csc(c2, t00), csc(-s2, t10));
    x[1] = cadd(csc(c2, t01), csc(-s2, t11));
    x[2] = cadd(csc(s2, t00), csc( c2, t10));
    x[3] = cadd(csc(s2, t01), csc( c2, t11));
    float c1, s1;
    __sincosf(0.5f * p[1], &s1, &c1);
    float2 u00 = cadd(csc(c1, x[0]), cni(s1, x[1]));
    float2 u01 = cadd(cni(s1, x[0]), csc(c1, x[1]));
    float2 u10 = cadd(csc(c1, x[2]), cni(s1, x[3]));
    float2 u11 = cadd(cni(s1, x[2]), csc(c1, x[3]));
    x[0] = cadd(csc(c1, u00), cni(s1, u10));
    x[1] = cadd(csc(c1, u01), cni(s1, u11));
    x[2] = cadd(cni(s1, u00), csc(c1, u10));
    x[3] = cadd(cni(s1, u01), csc(c1, u11));
}
__device__ __forceinline__ float fidelity_from(const float* l1, const float* l2) {
    float2 s1[4] = {make_float2(1.f, 0.f), make_float2(0.f, 0.f),
                    make_float2(0.f, 0.f), make_float2(0.f, 0.f)};
    applyU(l1, s1);
    applyU(l1 + 5, s1);
    float2 s2[4] = {make_float2(1.f, 0.f), make_float2(0.f, 0.f),
                    make_float2(0.f, 0.f), make_float2(0.f, 0.f)};
    applyU(l2, s2);
    applyU(l2 + 5, s2);
    float re = 0.f, im = 0.f;
    #pragma unroll
    for (int i = 0; i < 4; i++) {
        re += s2[i].x * s1[i].x + s2[i].y * s1[i].y;
        im += s2[i].x * s1[i].y - s2[i].y * s1[i].x;
    }
    return re * re + im * im;
}

// ---------------------------------------------------------------------------
// Fused kernel. SMEM map (phase-overlapped):
//   h1s:  [0, 116736)              128 x 228 fp32 (stride%32==4 -> no conflicts)
//   ring: [116736, ...)            L1: 2 x (16384 A + 28672 W1) = 90112
//                                  L2: 2 x 16384 (W2) ; L3: 2 x 8192 (W3)
//   h2s:  [149504, 217088)         128 x 132 fp32
//   Cs:   [116736, 151552)         128 x 68 fp32 (after L3)
//   w4s/b4s/Ls: [151552, ...)
// ---------------------------------------------------------------------------
#define H1OFF 0
#define H1S   228
#define RING  116736
#define S1SZ  45056
#define H2OFF 149504
#define H2S   132
#define CSOFF RING
#define CSS   68
#define L4OFF (RING + 34816)
#define SMTOT 217088

__global__ __launch_bounds__(512, 1)
void fused_all(const float* __restrict__ x,
               const unsigned char* __restrict__ w1f,
               const unsigned char* __restrict__ w2f,
               const unsigned char* __restrict__ w3f,
               const float* __restrict__ b1, const float* __restrict__ b2,
               const float* __restrict__ b3,
               const float* __restrict__ W4, const float* __restrict__ b4,
               float* __restrict__ out) {
    extern __shared__ __align__(16) char sm[];
    const uint32_t sb = smem_u32(sm);
    const int tid  = threadIdx.x;
    const int wid  = tid >> 5;
    const int lane = tid & 31;
    const int g    = lane >> 2;
    const int t    = lane & 3;
    const int mw   = wid & 3;       // rows [mw*32, mw*32+32)
    const int nw   = wid >> 2;      // n-warp 0..3
    const size_t m0 = (size_t)blockIdx.x * 128;

    float* h1s = (float*)(sm + H1OFF);
    float* h2s = (float*)(sm + H2OFF);

    float acc[2][7][4];

    // ================= Phase 1: L1 (K=300, N=224) =================
    #pragma unroll
    for (int mt = 0; mt < 2; mt++)
        #pragma unroll
        for (int j = 0; j < 7; j++)
            #pragma unroll
            for (int p = 0; p < 4; p++) acc[mt][j][p] = 0.f;

    auto stage1 = [&](int c, int slot) {
        const uint32_t bufb = sb + RING + slot * S1SZ;
        // A: 128 rows x 8 groups, fp32, zfill tails, XOR swizzle
        #pragma unroll
        for (int i = 0; i < 2; i++) {
            int f = tid + i * 512;
            int row = f >> 3, j = f & 7;
            int k0 = c * 32 + j * 4;
            int sz = (k0 + 4 <= 300) ? 16 : 0;
            const float* src = x + (m0 + row) * 300 + (sz ? k0 : 0);
            cpa16z(bufb + row * 128 + 16 * (j ^ (row & 7)), src, sz);
        }
        // W1: 224 rows x 8 entries
        #pragma unroll
        for (int i = 0; i < 4; i++) {
            int f = tid + i * 512;
            if (f < 224 * 8) {
                int row = f >> 3, e = f & 7;
                cpa16(bufb + 16384 + row * 128 + 16 * (e ^ ((row & 1) * 4)),
                      w1f + (size_t)row * 1280 + c * 128 + e * 16);
            }
        }
    };
    auto compute1 = [&](int slot) {
        const float* Asf = (const float*)(sm + RING + slot * S1SZ);
        const char*  Ws  = sm + RING + slot * S1SZ + 16384;
        #pragma unroll
        for (int s = 0; s < 2; s++) {
            uint32_t ua[4][4];
            #pragma unroll
            for (int ri = 0; ri < 4; ri++) {
                const float* rb = Asf + (mw * 32 + 8 * ri + g) * 32 + t;
                #pragma unroll
                for (int q = 0; q < 4; q++)
                    ua[ri][q] = to_tf32(rb[4 * ((4 * s + q) ^ g)]);
            }
            #pragma unroll
            for (int j = 0; j < 7; j++) {
                int wr = (nw * 7 + j) * 8 + g;
                uint4 bb = *(const uint4*)(Ws + wr * 128 +
                                           16 * ((s * 4 + t) ^ ((wr & 1) * 4)));
                mma_tf32(acc[0][j], ua[0][0], ua[1][0], ua[0][1], ua[1][1], bb.x, bb.y);
                mma_tf32(acc[1][j], ua[2][0], ua[3][0], ua[2][1], ua[3][1], bb.x, bb.y);
                mma_tf32(acc[0][j], ua[0][2], ua[1][2], ua[0][3], ua[1][3], bb.z, bb.w);
                mma_tf32(acc[1][j], ua[2][2], ua[3][2], ua[2][3], ua[3][3], bb.z, bb.w);
            }
        }
    };

    stage1(0, 0); CP_COMMIT();
    stage1(1, 1); CP_COMMIT();
    for (int c = 0; c < 10; ++c) {
        if (c + 1 < 10) { CP_WAIT1(); } else { CP_WAIT0(); }
        __syncthreads();
        compute1(c & 1);
        __syncthreads();
        if (c + 2 < 10) { stage1(c + 2, c & 1); CP_COMMIT(); }
    }

    // epilogue -> h1s (bias + relu); cols 200..223 become exactly 0
    #pragma unroll
    for (int mt = 0; mt < 2; mt++) {
        int r = mw * 32 + mt * 16 + g;
        #pragma unroll
        for (int j = 0; j < 7; j++) {
            int n = (nw * 7 + j) * 8 + 2 * t;
            float bx = (n     < 200) ? b1[n]     : 0.f;
            float by = (n + 1 < 200) ? b1[n + 1] : 0.f;
            *(float2*)(h1s + r * H1S + n) =
                make_float2(fmaxf(acc[0][j][2 * mt + 0] + bx, 0.f) * 0.f +
                            fmaxf(acc[mt][j][0] + bx, 0.f),
                            fmaxf(acc[mt][j][1] + by, 0.f));
            *(float2*)(h1s + (r + 8) * H1S + n) =
                make_float2(fmaxf(acc[mt][j][2] + bx, 0.f),
                            fmaxf(acc[mt][j][3] + by, 0.f));
        }
    }
    __syncthreads();

    // ================= Phase 2: L2 (K=224 from h1s, N=128) =================
    #pragma unroll
    for (int mt = 0; mt < 2; mt++)
        #pragma unroll
        for (int j = 0; j < 7; j++)
            #pragma unroll
            for (int p = 0; p < 4; p++) acc[mt][j][p] = 0.f;

    auto stage2 = [&](int c, int slot) {
        const uint32_t bufb = sb + RING + slot * 16384;
        #pragma unroll
        for (int i = 0; i < 2; i++) {
            int f = tid + i * 512;   // 128*8 = 1024 entries
            int row = f >> 3, e = f & 7;
            cpa16(bufb + row * 128 + 16 * (e ^ ((row & 1) * 4)),
                  w2f + (size_t)row * 896 + c * 128 + e * 16);
        }
    };
    auto compute2 = [&](int c, int slot) {
        const char* Ws = sm + RING + slot * 16384;
        #pragma unroll
        for (int s = 0; s < 2; s++) {
            uint32_t ua[4][4];
            #pragma unroll
            for (int ri = 0; ri < 4; ri++) {
                const float* rb = h1s + (mw * 32 + 8 * ri + g) * H1S +
                                  c * 32 + s * 16 + t;
                #pragma unroll
                for (int q = 0; q < 4; q++)
                    ua[ri][q] = to_tf32(rb[q * 4]);
            }
            #pragma unroll
            for (int j = 0; j < 4; j++) {
                int wr = (nw * 4 + j) * 8 + g;
                uint4 bb = *(const uint4*)(Ws + wr * 128 +
                                           16 * ((s * 4 + t) ^ ((wr & 1) * 4)));
                mma_tf32(acc[0][j], ua[0][0], ua[1][0], ua[0][1], ua[1][1], bb.x, bb.y);
                mma_tf32(acc[1][j], ua[2][0], ua[3][0], ua[2][1], ua[3][1], bb.x, bb.y);
                mma_tf32(acc[0][j], ua[0][2], ua[1][2], ua[0][3], ua[1][3], bb.z, bb.w);
                mma_tf32(acc[1][j], ua[2][2], ua[3][2], ua[2][3], ua[3][3], bb.z, bb.w);
            }
        }
    };

    stage2(0, 0); CP_COMMIT();
    stage2(1, 1); CP_COMMIT();
    for (int c = 0; c < 7; ++c) {
        if (c + 1 < 7) { CP_WAIT1(); } else { CP_WAIT0(); }
        __syncthreads();
        compute2(c, c & 1);
        __syncthreads();
        if (c + 2 < 7) { stage2(c + 2, c & 1); CP_COMMIT(); }
    }

    // epilogue -> h2s; cols 100..127 exactly 0
    #pragma unroll
    for (int mt = 0; mt < 2; mt++) {
        int r = mw * 32 + mt * 16 + g;
        #pragma unroll
        for (int j = 0; j < 4; j++) {
            int n = (nw * 4 + j) * 8 + 2 * t;
            float bx = (n     < 100) ? b2[n]     : 0.f;
            float by = (n + 1 < 100) ? b2[n + 1] : 0.f;
            *(float2*)(h2s + r * H2S + n) =
                make_float2(fmaxf(acc[mt][j][0] + bx, 0.f),
                            fmaxf(acc[mt][j][1] + by, 0.f));
            *(float2*)(h2s + (r + 8) * H2S + n) =
                make_float2(fmaxf(acc[mt][j][2] + bx, 0.f),
                            fmaxf(acc[mt][j][3] + by, 0.f));
        }
    }
    __syncthreads();

    // ================= Phase 3: L3 (K=128 from h2s, N=64) =================
    #pragma unroll
    for (int mt = 0; mt < 2; mt++)
        #pragma unroll
        for (int j = 0; j < 2; j++)
            #pragma unroll
            for (int p = 0; p < 4; p++) acc[mt][j][p] = 0.f;

    auto stage3 = [&](int c, int slot) {
        const uint32_t bufb = sb + RING + slot * 8192;
        int f = tid;                 // 64*8 = 512 entries
        int row = f >> 3, e = f & 7;
        cpa16(bufb + row * 128 + 16 * (e ^ ((row & 1) * 4)),
              w3f + (size_t)row * 512 + c * 128 + e * 16);
    };
    auto compute3 = [&](int c, int slot) {
        const char* Ws = sm + RING + slot * 8192;
        #pragma unroll
        for (int s = 0; s < 2; s++) {
            uint32_t ua[4][4];
            #pragma unroll
            for (int ri = 0; ri < 4; ri++) {
                const float* rb = h2s + (mw * 32 + 8 * ri + g) * H2S +
                                  c * 32 + s * 16 + t;
                #pragma unroll
                for (int q = 0; q < 4; q++)
                    ua[ri][q] = to_tf32(rb[q * 4]);
            }
            #pragma unroll
            for (int j = 0; j < 2; j++) {
                int wr = (nw * 2 + j) * 8 + g;
                uint4 bb = *(const uint4*)(Ws + wr * 128 +
                                           16 * ((s * 4 + t) ^ ((wr & 1) * 4)));
                mma_tf32(acc[0][j], ua[0][0], ua[1][0], ua[0][1], ua[1][1], bb.x, bb.y);
                mma_tf32(acc[1][j], ua[2][0], ua[3][0], ua[2][1], ua[3][1], bb.x, bb.y);
                mma_tf32(acc[0][j], ua[0][2], ua[1][2], ua[0][3], ua[1][3], bb.z, bb.w);
                mma_tf32(acc[1][j], ua[2][2], ua[3][2], ua[2][3], ua[3][3], bb.z, bb.w);
            }
        }
    };

    stage3(0, 0); CP_COMMIT();
    stage3(1, 1); CP_COMMIT();
    for (int c = 0; c < 4; ++c) {
        if (c + 1 < 4) { CP_WAIT1(); } else { CP_WAIT0(); }
        __syncthreads();
        compute3(c, c & 1);
        __syncthreads();
        if (c + 2 < 4) { stage3(c + 2, c & 1); CP_COMMIT(); }
    }
    __syncthreads();   // W3 ring dead; Cs overlaps it

    // epilogue -> Cs (bias + relu); layer-3 HAS relu per reference mlp()
    float* Cs = (float*)(sm + CSOFF);
    #pragma unroll
    for (int mt = 0; mt < 2; mt++) {
        int r = mw * 32 + mt * 16 + g;
        #pragma unroll
        for (int j = 0; j < 2; j++) {
            int n = (nw * 2 + j) * 8 + 2 * t;
            float bx = (n     < 50) ? b3[n]     : 0.f;
            float by = (n + 1 < 50) ? b3[n + 1] : 0.f;
            *(float2*)(Cs + r * CSS + n) =
                make_float2(fmaxf(acc[mt][j][0] + bx, 0.f),
                            fmaxf(acc[mt][j][1] + by, 0.f));
            *(float2*)(Cs + (r + 8) * CSS + n) =
                make_float2(fmaxf(acc[mt][j][2] + bx, 0.f),
                            fmaxf(acc[mt][j][3] + by, 0.f));
        }
    }

    // ================= Phase 4: layer4 (50->10) + fidelity =================
    float* w4s = (float*)(sm + L4OFF);          // 500
    float* b4s = w4s + 500;                     // 10
    float* Ls  = (float*)(sm + L4OFF + 2048);   // [128][11]
    for (int i = tid; i < 500; i += 512) w4s[i] = W4[i];
    if (tid < 10) b4s[tid] = b4[tid];
    __syncthreads();

    if (tid < 128) {
        float l[10];
        #pragma unroll
        for (int j = 0; j < 10; j++) l[j] = b4s[j];
        #pragma unroll 5
        for (int k = 0; k < 50; k++) {
            float hv = Cs[tid * CSS + k];
            #pragma unroll
            for (int j = 0; j < 10; j++) l[j] = fmaf(w4s[j * 50 + k], hv, l[j]);
        }
        #pragma unroll
        for (int j = 0; j < 10; j++) Ls[tid * 11 + j] = l[j];
    }
    __syncthreads();
    if (tid < 64) {
        out[(size_t)blockIdx.x * 64 + tid] =
            fidelity_from(Ls + 2 * tid * 11, Ls + (2 * tid + 1) * 11);
    }
}

// ---------------------------------------------------------------------------
extern "C" void kernel_launch(void* const* d_in, const int* in_sizes, int n_in,
                              void* d_out, int out_size) {
    const float* x  = (const float*)d_in[0];
    const float* W1 = (const float*)d_in[1];
    const float* b1 = (const float*)d_in[2];
    const float* W2 = (const float*)d_in[3];
    const float* b2 = (const float*)d_in[4];
    const float* W3 = (const float*)d_in[5];
    const float* b3 = (const float*)d_in[6];
    const float* W4 = (const float*)d_in[7];
    const float* b4 = (const float*)d_in[8];

    unsigned char *w1f, *w2f, *w3f;
    cudaGetSymbolAddress((void**)&w1f, g_w1f);
    cudaGetSymbolAddress((void**)&w2f, g_w2f);
    cudaGetSymbolAddress((void**)&w3f, g_w3f);

    prep_frag<<<(224 * 20 + 255) / 256, 256>>>(W1, w1f, 224, 200, 300, 20);
    prep_frag<<<(128 * 14 + 255) / 256, 256>>>(W2, w2f, 128, 100, 200, 14);
    prep_frag<<<(64  *  8 + 255) / 256, 256>>>(W3, w3f, 64,  50,  100, 8);

    cudaFuncSetAttribute(fused_all,
                         cudaFuncAttributeMaxDynamicSharedMemorySize, SMTOT);
    fused_all<<<MROWS / 128, 512, SMTOT>>>(x, w1f, w2f, w3f,
                                           b1, b2, b3, W4, b4, (float*)d_out);
}

// round 10
// speedup vs baseline: 1.0563x; 1.0563x over previous
#include <cuda_runtime.h>
#include <math.h>
#include <cstdint>

// ---------------------------------------------------------------------------
// PreQ round 10:
//   L1 = round-8 kernel verbatim (125.9us measured, 49% tensor): x fp32 ->
//        h1 fp32 [M,200], y-interleaved N-split, 3-stage cp.async ring.
//   tail_fused = L2 (h1 gmem -> h2 SMEM) + L3 (h2 SMEM) + layer4 + quantum,
//        64 rows/CTA, 2048 CTAs, 256 thr, 105KB smem -> 2 CTAs/SM.
// tf32 mma.sync m16n8k8 throughout (rel_err 1.28e-4, validated R6-R9).
// ---------------------------------------------------------------------------

#define MROWS 131072   // 2 * 65536

__device__ float g_h1[(size_t)MROWS * 200];
__device__ __align__(16) unsigned char g_w1f[224 * 1280];
__device__ __align__(16) unsigned char g_w2f[128 * 896];
__device__ __align__(16) unsigned char g_w3f[64 * 512];

// ---------------- helpers ----------------
__device__ __forceinline__ uint32_t smem_u32(const void* p) {
    uint32_t a;
    asm("{ .reg .u64 t; cvta.to.shared.u64 t, %1; cvt.u32.u64 %0, t; }"
        : "=r"(a) : "l"(p));
    return a;
}
__device__ __forceinline__ void cpa16(uint32_t dst, const void* src) {
    asm volatile("cp.async.cg.shared.global [%0], [%1], 16;"
                 :: "r"(dst), "l"(src) : "memory");
}
__device__ __forceinline__ void cpa16z(uint32_t dst, const void* src, int sz) {
    asm volatile("cp.async.cg.shared.global [%0], [%1], 16, %2;"
                 :: "r"(dst), "l"(src), "r"(sz) : "memory");
}
#define CP_COMMIT() asm volatile("cp.async.commit_group;" ::: "memory")
#define CP_WAIT0()  asm volatile("cp.async.wait_group 0;" ::: "memory")
#define CP_WAIT1()  asm volatile("cp.async.wait_group 1;" ::: "memory")

__device__ __forceinline__ uint32_t to_tf32(float f) {
    uint32_t r;
    asm("cvt.rna.tf32.f32 %0, %1;" : "=r"(r) : "f"(f));
    return r;
}
__device__ __forceinline__ void mma_tf32(float c[4],
                                         uint32_t a0, uint32_t a1,
                                         uint32_t a2, uint32_t a3,
                                         uint32_t b0, uint32_t b1) {
    asm volatile(
        "mma.sync.aligned.m16n8k8.row.col.f32.tf32.tf32.f32 "
        "{%0,%1,%2,%3}, {%4,%5,%6,%7}, {%8,%9}, {%0,%1,%2,%3};"
        : "+f"(c[0]), "+f"(c[1]), "+f"(c[2]), "+f"(c[3])
        : "r"(a0), "r"(a1), "r"(a2), "r"(a3), "r"(b0), "r"(b1));
}

// ---------------------------------------------------------------------------
// prep: W[src_rows, K] fp32 -> frag image [nrows_pad][nblk*64B], RN tf32.
// ---------------------------------------------------------------------------
__global__ void prep_frag(const float* __restrict__ S,
                          unsigned char* __restrict__ D,
                          int nrows_pad, int src_rows, int K, int nblk) {
    int f = blockIdx.x * blockDim.x + threadIdx.x;
    if (f >= nrows_pad * nblk) return;
    int row = f / nblk, eb = f - row * nblk;
    int k0 = eb * 16;
    float v[16];
    #pragma unroll
    for (int i = 0; i < 16; i++) v[i] = 0.f;
    if (row < src_rows) {
        #pragma unroll
        for (int i = 0; i < 4; i++) {
            int k = k0 + i * 4;
            if (k < K) {
                float4 q = *(const float4*)(S + (size_t)row * K + k);
                v[i * 4 + 0] = q.x; v[i * 4 + 1] = q.y;
                v[i * 4 + 2] = q.z; v[i * 4 + 3] = q.w;
            }
        }
    }
    uint32_t u[16];
    #pragma unroll
    for (int i = 0; i < 16; i++) u[i] = to_tf32(v[i]);
    unsigned char* dst = D + (size_t)row * (nblk * 64) + (size_t)eb * 64;
    #pragma unroll
    for (int tp = 0; tp < 4; tp++)
        *(uint4*)(dst + tp * 16) =
            make_uint4(u[tp], u[tp + 4], u[tp + 8], u[tp + 12]);
}

// ---------------- quantum math (verified rounds 1-9) ----------------
__device__ __forceinline__ float2 cadd(float2 a, float2 b) {
    return make_float2(a.x + b.x, a.y + b.y);
}
__device__ __forceinline__ float2 csc(float s, float2 a) {
    return make_float2(s * a.x, s * a.y);
}
__device__ __forceinline__ float2 cni(float s, float2 a) {
    return make_float2(s * a.y, -s * a.x);
}
__device__ void applyU(const float* __restrict__ p, float2 x[4]) {
    float c4, s4;
    __sincosf(0.5f * p[4], &s4, &c4);
    float2 y1 = make_float2(c4 * x[1].x + s4 * x[3].y,
                            c4 * x[1].y - s4 * x[3].x);
    float2 y3 = make_float2(s4 * x[1].y + c4 * x[3].x,
                           -s4 * x[1].x + c4 * x[3].y);
    x[1] = y1; x[3] = y3;
    float c2, s2, c3, s3;
    __sincosf(0.5f * p[2], &s2, &c2);
    __sincosf(0.5f * p[3], &s3, &c3);
    float2 t00 = cadd(csc(c3, x[0]), csc(-s3, x[1]));
    float2 t01 = cadd(csc(s3, x[0]), csc( c3, x[1]));
    float2 t10 = cadd(csc(c3, x[2]), csc(-s3, x[3]));
    float2 t11 = cadd(csc(s3, x[2]), csc( c3, x[3]));
    x[0] = cadd(csc(c2, t00), csc(-s2, t10));
    x[1] = cadd(csc(c2, t01), csc(-s2, t11));
    x[2] = cadd(csc(s2, t00), csc( c2, t10));
    x[3] = cadd(csc(s2, t01), csc( c2, t11));
    float c1, s1;
    __sincosf(0.5f * p[1], &s1, &c1);
    float2 u00 = cadd(csc(c1, x[0]), cni(s1, x[1]));
    float2 u01 = cadd(cni(s1, x[0]), csc(c1, x[1]));
    float2 u10 = cadd(csc(c1, x[2]), cni(s1, x[3]));
    float2 u11 = cadd(cni(s1, x[2]), csc(c1, x[3]));
    x[0] = cadd(csc(c1, u00), cni(s1, u10));
    x[1] = cadd(csc(c1, u01), cni(s1, u11));
    x[2] = cadd(cni(s1, u00), csc(c1, u10));
    x[3] = cadd(cni(s1, u01), csc(c1, u11));
}
__device__ __forceinline__ float fidelity_from(const float* l1, const float* l2) {
    float2 s1[4] = {make_float2(1.f, 0.f), make_float2(0.f, 0.f),
                    make_float2(0.f, 0.f), make_float2(0.f, 0.f)};
    applyU(l1, s1);
    applyU(l1 + 5, s1);
    float2 s2[4] = {make_float2(1.f, 0.f), make_float2(0.f, 0.f),
                    make_float2(0.f, 0.f), make_float2(0.f, 0.f)};
    applyU(l2, s2);
    applyU(l2 + 5, s2);
    float re = 0.f, im = 0.f;
    #pragma unroll
    for (int i = 0; i < 4; i++) {
        re += s2[i].x * s1[i].x + s2[i].y * s1[i].y;
        im += s2[i].x * s1[i].y - s2[i].y * s1[i].x;
    }
    return re * re + im * im;
}

// ---------------------------------------------------------------------------
// L1 GEMM (round-8 verbatim): 128 rows/CTA, 8 warps = 4m x 2n (NWT=7),
// y-interleaved N-split, 3-stage cp.async ring, fp32 out with ReLU.
// ---------------------------------------------------------------------------
__global__ __launch_bounds__(256, 2)
void gemm_l1(const float* __restrict__ A,
             const unsigned char* __restrict__ Wf,
             const float* __restrict__ bias, float* __restrict__ C) {
    extern __shared__ __align__(16) char sm[];
    constexpr int NWT   = 7;
    constexpr int NTC   = 112;
    constexpr int ABY   = 128 * 128;
    constexpr int STAGE = ABY + NTC * 128;   // 30720
    constexpr int K     = 300, Ntrue = 200, nch = 10;

    const uint32_t sb = smem_u32(sm);
    const int tid  = threadIdx.x;
    const int wid  = tid >> 5;
    const int lane = tid & 31;
    const int g    = lane >> 2;
    const int t    = lane & 3;
    const int mw   = wid & 3;
    const int nw   = wid >> 2;
    const int bx   = blockIdx.x;
    const size_t m0 = (size_t)(bx >> 1) * 128;
    const int n0   = (bx & 1) * NTC;

    float acc[2][NWT][4];
    #pragma unroll
    for (int mt = 0; mt < 2; mt++)
        #pragma unroll
        for (int j = 0; j < NWT; j++)
            #pragma unroll
            for (int p = 0; p < 4; p++) acc[mt][j][p] = 0.f;

    auto stage = [&](int c, int slot) {
        const uint32_t bufb = sb + slot * STAGE;
        #pragma unroll
        for (int i = 0; i < 4; i++) {
            int f = tid + i * 256;
            int row = f >> 3, j = f & 7;
            int k0 = c * 32 + j * 4;
            int sz = (k0 + 4 <= K) ? 16 : 0;
            const float* src = A + (m0 + row) * (size_t)K + (sz ? k0 : 0);
            cpa16z(bufb + row * 128 + 16 * (j ^ (row & 7)), src, sz);
        }
        #pragma unroll
        for (int i = 0; i < 4; i++) {
            int f = tid + i * 256;
            if (f < NTC * 8) {
                int row = f >> 3, e = f & 7;
                cpa16(bufb + ABY + row * 128 + 16 * (e ^ ((row & 1) * 4)),
                      Wf + (size_t)(n0 + row) * 1280 + c * 128 + e * 16);
            }
        }
    };
    auto compute = [&](int slot) {
        const float* Asf = (const float*)(sm + slot * STAGE);
        const char*  Ws  = sm + slot * STAGE + ABY;
        #pragma unroll
        for (int s = 0; s < 2; s++) {
            uint32_t ua[4][4];
            #pragma unroll
            for (int ri = 0; ri < 4; ri++) {
                const float* rb = Asf + (mw * 32 + 8 * ri + g) * 32 + t;
                #pragma unroll
                for (int q = 0; q < 4; q++)
                    ua[ri][q] = to_tf32(rb[4 * ((4 * s + q) ^ g)]);
            }
            #pragma unroll
            for (int j = 0; j < NWT; j++) {
                int wr = (nw * NWT + j) * 8 + g;
                uint4 bb = *(const uint4*)(Ws + wr * 128 +
                                           16 * ((s * 4 + t) ^ ((wr & 1) * 4)));
                mma_tf32(acc[0][j], ua[0][0], ua[1][0], ua[0][1], ua[1][1], bb.x, bb.y);
                mma_tf32(acc[1][j], ua[2][0], ua[3][0], ua[2][1], ua[3][1], bb.x, bb.y);
                mma_tf32(acc[0][j], ua[0][2], ua[1][2], ua[0][3], ua[1][3], bb.z, bb.w);
                mma_tf32(acc[1][j], ua[2][2], ua[3][2], ua[2][3], ua[3][3], bb.z, bb.w);
            }
        }
    };

    stage(0, 0); CP_COMMIT();
    stage(1, 1); CP_COMMIT();
    for (int c = 0; c < nch; ++c) {
        if (c + 1 < nch) { CP_WAIT1(); } else { CP_WAIT0(); }
        __syncthreads();
        compute(c - (c / 3) * 3);
        if (c + 2 < nch) { stage(c + 2, (c + 2) % 3); CP_COMMIT(); }
    }
    __syncthreads();

    #pragma unroll
    for (int mt = 0; mt < 2; mt++) {
        const size_t r = m0 + mw * 32 + mt * 16 + g;
        #pragma unroll
        for (int j = 0; j < NWT; j++) {
            int n = n0 + (nw * NWT + j) * 8 + 2 * t;
            if (n < Ntrue) {
                float2 b2 = *(const float2*)(bias + n);
                float v0 = fmaxf(acc[mt][j][0] + b2.x, 0.f);
                float v1 = fmaxf(acc[mt][j][1] + b2.y, 0.f);
                float v2 = fmaxf(acc[mt][j][2] + b2.x, 0.f);
                float v3 = fmaxf(acc[mt][j][3] + b2.y, 0.f);
                *(float2*)(C + r * Ntrue + n)       = make_float2(v0, v1);
                *(float2*)(C + (r + 8) * Ntrue + n) = make_float2(v2, v3);
            }
        }
    }
}

// ---------------------------------------------------------------------------
// tail_fused: 64 rows/CTA (2048 CTAs, 256 thr, 8 warps = 2m x 4n).
//   L2: A = h1 gmem [M,200], 3-stage ring (A 8KB + W2 16KB per slot),
//       -> h2s SMEM 64x132 (cols 100..127 = 0).
//   L3: A = h2s (K=128, 4 chunks), W3 fully resident (32KB, reused ring).
//   layer4 (50->10) + quantum fidelity -> out.
// SMEM: ring [0,73728) | h2s [73728,107520). After L2: W3 [0,32768),
//       Cs [32768,50176), w4s/b4s [50176,52224), Ls [53248,56064).
// ---------------------------------------------------------------------------
#define T_RING  0
#define T_S2SZ  24576        // 64*128 A + 128*128 W2
#define T_H2OFF 73728
#define T_H2S   132
#define T_W3OFF 0
#define T_CSOFF 32768
#define T_CSS   68
#define T_W4OFF 50176
#define T_LSOFF 53248
#define T_SMTOT 107520

__global__ __launch_bounds__(256, 2)
void tail_fused(const float* __restrict__ h1,
                const unsigned char* __restrict__ w2f,
                const unsigned char* __restrict__ w3f,
                const float* __restrict__ b2, const float* __restrict__ b3,
                const float* __restrict__ W4, const float* __restrict__ b4,
                float* __restrict__ out) {
    extern __shared__ __align__(16) char sm[];
    const uint32_t sb = smem_u32(sm);
    const int tid  = threadIdx.x;
    const int wid  = tid >> 5;
    const int lane = tid & 31;
    const int g    = lane >> 2;
    const int t    = lane & 3;
    const int mw   = wid & 1;       // m-warp: rows [mw*32, mw*32+32)
    const int nw   = wid >> 1;      // n-warp 0..3
    const size_t m0 = (size_t)blockIdx.x * 64;

    float* h2s = (float*)(sm + T_H2OFF);

    // ================= L2: K=200, N=128 (NWT=4/warp) =================
    float acc[2][4][4];
    #pragma unroll
    for (int mt = 0; mt < 2; mt++)
        #pragma unroll
        for (int j = 0; j < 4; j++)
            #pragma unroll
            for (int p = 0; p < 4; p++) acc[mt][j][p] = 0.f;

    auto stage2 = [&](int c, int slot) {
        const uint32_t bufb = sb + T_RING + slot * T_S2SZ;
        // A: 64 rows x 8 groups = 512 entries (1/thread... 2 iters of 256)
        #pragma unroll
        for (int i = 0; i < 2; i++) {
            int f = tid + i * 256;
            int row = f >> 3, j = f & 7;
            int k0 = c * 32 + j * 4;
            int sz = (k0 + 4 <= 200) ? 16 : 0;
            const float* src = h1 + (m0 + row) * 200 + (sz ? k0 : 0);
            cpa16z(bufb + row * 128 + 16 * (j ^ (row & 7)), src, sz);
        }
        // W2: 128 rows x 8 entries = 1024
        #pragma unroll
        for (int i = 0; i < 4; i++) {
            int f = tid + i * 256;
            int row = f >> 3, e = f & 7;
            cpa16(bufb + 64 * 128 + row * 128 + 16 * (e ^ ((row & 1) * 4)),
                  w2f + (size_t)row * 896 + c * 128 + e * 16);
        }
    };
    auto compute2 = [&](int slot) {
        const float* Asf = (const float*)(sm + T_RING + slot * T_S2SZ);
        const char*  Ws  = sm + T_RING + slot * T_S2SZ + 64 * 128;
        #pragma unroll
        for (int s = 0; s < 2; s++) {
            uint32_t ua[4][4];
            #pragma unroll
            for (int ri = 0; ri < 4; ri++) {
                const float* rb = Asf + (mw * 32 + 8 * ri + g) * 32 + t;
                #pragma unroll
                for (int q = 0; q < 4; q++)
                    ua[ri][q] = to_tf32(rb[4 * ((4 * s + q) ^ g)]);
            }
            #pragma unroll
            for (int j = 0; j < 4; j++) {
                int wr = (nw * 4 + j) * 8 + g;
                uint4 bb = *(const uint4*)(Ws + wr * 128 +
                                           16 * ((s * 4 + t) ^ ((wr & 1) * 4)));
                mma_tf32(acc[0][j], ua[0][0], ua[1][0], ua[0][1], ua[1][1], bb.x, bb.y);
                mma_tf32(acc[1][j], ua[2][0], ua[3][0], ua[2][1], ua[3][1], bb.x, bb.y);
                mma_tf32(acc[0][j], ua[0][2], ua[1][2], ua[0][3], ua[1][3], bb.z, bb.w);
                mma_tf32(acc[1][j], ua[2][2], ua[3][2], ua[2][3], ua[3][3], bb.z, bb.w);
            }
        }
    };

    stage2(0, 0); CP_COMMIT();
    stage2(1, 1); CP_COMMIT();
    for (int c = 0; c < 7; ++c) {
        if (c + 1 < 7) { CP_WAIT1(); } else { CP_WAIT0(); }
        __syncthreads();
        compute2(c - (c / 3) * 3);
        if (c + 2 < 7) { stage2(c + 2, (c + 2) % 3); CP_COMMIT(); }
    }
    __syncthreads();   // ring dead; safe to stage W3 below

    // stage ALL of W3 (64 rows x 4 chunks x 128B) into [0, 32768)
    {
        // 2048 entries of 16B, 8 per thread
        #pragma unroll
        for (int i = 0; i < 8; i++) {
            int f = tid + i * 256;
            int c = f >> 9, rem = f & 511;
            int row = rem >> 3, e = rem & 7;
            cpa16(sb + T_W3OFF + c * 8192 + row * 128 + 16 * (e ^ ((row & 1) * 4)),
                  w3f + (size_t)row * 512 + c * 128 + e * 16);
        }
        CP_COMMIT();
    }

    // L2 epilogue -> h2s (bias + relu); cols 100..127 = relu(0+0) = 0
    #pragma unroll
    for (int mt = 0; mt < 2; mt++) {
        int r = mw * 32 + mt * 16 + g;
        #pragma unroll
        for (int j = 0; j < 4; j++) {
            int n = (nw * 4 + j) * 8 + 2 * t;
            float bx = (n     < 100) ? b2[n]     : 0.f;
            float by = (n + 1 < 100) ? b2[n + 1] : 0.f;
            *(float2*)(h2s + r * T_H2S + n) =
                make_float2(fmaxf(acc[mt][j][0] + bx, 0.f),
                            fmaxf(acc[mt][j][1] + by, 0.f));
            *(float2*)(h2s + (r + 8) * T_H2S + n) =
                make_float2(fmaxf(acc[mt][j][2] + bx, 0.f),
                            fmaxf(acc[mt][j][3] + by, 0.f));
        }
    }
    CP_WAIT0();
    __syncthreads();

    // ================= L3: K=128 from h2s, N=64 (NWT=2/warp) =================
    float acc3[2][2][4];
    #pragma unroll
    for (int mt = 0; mt < 2; mt++)
        #pragma unroll
        for (int j = 0; j < 2; j++)
            #pragma unroll
            for (int p = 0; p < 4; p++) acc3[mt][j][p] = 0.f;

    const char* W3s = sm + T_W3OFF;
    #pragma unroll
    for (int c = 0; c < 4; ++c) {
        #pragma unroll
        for (int s = 0; s < 2; s++) {
            uint32_t ua[4][4];
            #pragma unroll
            for (int ri = 0; ri < 4; ri++) {
                const float* rb = h2s + (mw * 32 + 8 * ri + g) * T_H2S +
                                  c * 32 + s * 16 + t;
                #pragma unroll
                for (int q = 0; q < 4; q++)
                    ua[ri][q] = to_tf32(rb[q * 4]);
            }
            #pragma unroll
            for (int j = 0; j < 2; j++) {
                int wr = (nw * 2 + j) * 8 + g;
                uint4 bb = *(const uint4*)(W3s + c * 8192 + wr * 128 +
                                           16 * ((s * 4 + t) ^ ((wr & 1) * 4)));
                mma_tf32(acc3[0][j], ua[0][0], ua[1][0], ua[0][1], ua[1][1], bb.x, bb.y);
                mma_tf32(acc3[1][j], ua[2][0], ua[3][0], ua[2][1], ua[3][1], bb.x, bb.y);
                mma_tf32(acc3[0][j], ua[0][2], ua[1][2], ua[0][3], ua[1][3], bb.z, bb.w);
                mma_tf32(acc3[1][j], ua[2][2], ua[3][2], ua[2][3], ua[3][3], bb.z, bb.w);
            }
        }
    }
    __syncthreads();   // W3s region about to be reused as Cs/w4s

    // L3 epilogue -> Cs (bias + relu)
    float* Cs = (float*)(sm + T_CSOFF);
    #pragma unroll
    for (int mt = 0; mt < 2; mt++) {
        int r = mw * 32 + mt * 16 + g;
        #pragma unroll
        for (int j = 0; j < 2; j++) {
            int n = (nw * 2 + j) * 8 + 2 * t;
            float bx = (n     < 50) ? b3[n]     : 0.f;
            float by = (n + 1 < 50) ? b3[n + 1] : 0.f;
            *(float2*)(Cs + r * T_CSS + n) =
                make_float2(fmaxf(acc3[mt][j][0] + bx, 0.f),
                            fmaxf(acc3[mt][j][1] + by, 0.f));
            *(float2*)(Cs + (r + 8) * T_CSS + n) =
                make_float2(fmaxf(acc3[mt][j][2] + bx, 0.f),
                            fmaxf(acc3[mt][j][3] + by, 0.f));
        }
    }

    // ================= layer4 (50->10) + fidelity =================
    float* w4s = (float*)(sm + T_W4OFF);       // 500
    float* b4s = w4s + 500;                    // 10
    float* Ls  = (float*)(sm + T_LSOFF);       // [64][11]
    for (int i = tid; i < 500; i += 256) w4s[i] = W4[i];
    if (tid < 10) b4s[tid] = b4[tid];
    __syncthreads();

    if (tid < 64) {
        float l[10];
        #pragma unroll
        for (int j = 0; j < 10; j++) l[j] = b4s[j];
        #pragma unroll 5
        for (int k = 0; k < 50; k++) {
            float hv = Cs[tid * T_CSS + k];
            #pragma unroll
            for (int j = 0; j < 10; j++) l[j] = fmaf(w4s[j * 50 + k], hv, l[j]);
        }
        #pragma unroll
        for (int j = 0; j < 10; j++) Ls[tid * 11 + j] = l[j];
    }
    __syncthreads();
    if (tid < 32) {
        out[(size_t)blockIdx.x * 32 + tid] =
            fidelity_from(Ls + 2 * tid * 11, Ls + (2 * tid + 1) * 11);
    }
}

// ---------------------------------------------------------------------------
extern "C" void kernel_launch(void* const* d_in, const int* in_sizes, int n_in,
                              void* d_out, int out_size) {
    const float* x  = (const float*)d_in[0];
    const float* W1 = (const float*)d_in[1];
    const float* b1 = (const float*)d_in[2];
    const float* W2 = (const float*)d_in[3];
    const float* b2 = (const float*)d_in[4];
    const float* W3 = (const float*)d_in[5];
    const float* b3 = (const float*)d_in[6];
    const float* W4 = (const float*)d_in[7];
    const float* b4 = (const float*)d_in[8];

    float* h1;
    unsigned char *w1f, *w2f, *w3f;
    cudaGetSymbolAddress((void**)&h1,  g_h1);
    cudaGetSymbolAddress((void**)&w1f, g_w1f);
    cudaGetSymbolAddress((void**)&w2f, g_w2f);
    cudaGetSymbolAddress((void**)&w3f, g_w3f);

    prep_frag<<<(224 * 20 + 255) / 256, 256>>>(W1, w1f, 224, 200, 300, 20);
    prep_frag<<<(128 * 14 + 255) / 256, 256>>>(W2, w2f, 128, 100, 200, 14);
    prep_frag<<<(64  *  8 + 255) / 256, 256>>>(W3, w3f, 64,  50,  100, 8);

    constexpr int SML1 = 3 * (128 * 128 + 112 * 128);  // 92160
    cudaFuncSetAttribute(gemm_l1,
                         cudaFuncAttributeMaxDynamicSharedMemorySize, SML1);
    cudaFuncSetAttribute(tail_fused,
                         cudaFuncAttributeMaxDynamicSharedMemorySize, T_SMTOT);

    gemm_l1<<<(MROWS / 128) * 2, 256, SML1>>>(x, w1f, b1, h1);
    tail_fused<<<MROWS / 64, 256, T_SMTOT>>>(h1, w2f, w3f,
                                             b2, b3, W4, b4, (float*)d_out);
}